// round 1
// baseline (speedup 1.0000x reference)
#include <cuda_runtime.h>
#include <cuda_bf16.h>

// Dequant: groups of 17 int32 (16 "byte" ints -> 32 nibbles, 1 scale int).
// out[g*32 + i] = (nibble_i - 8) / 12 * exp2(clamp(scale-127, -126, 127))
//
// One thread produces one float4 (4 consecutive outputs = 2 input ints).
// 8 threads per group; stores fully coalesced (STG.128), scale load is a
// broadcast within each 8-lane cohort.

__global__ void __launch_bounds__(256) dequant_mxfp4_kernel(
    const int* __restrict__ packed,
    float4* __restrict__ out,
    int num_quads)
{
    int q = blockIdx.x * blockDim.x + threadIdx.x;
    if (q >= num_quads) return;

    int g   = q >> 3;        // group index
    int sub = q & 7;         // which pair-of-ints within group
    int base = g * 17;       // max ~71.3M, fits int32

    int v0 = __ldg(packed + base + sub * 2);
    int v1 = __ldg(packed + base + sub * 2 + 1);
    int s  = __ldg(packed + base + 16);

    // exp2(clip(s-127,-126,127)) == bit-exact float with exponent field clamp(s,1,254)
    int e = min(max(s, 1), 254);
    float scale = __int_as_float(e << 23) * (1.0f / 12.0f);

    float4 r;
    r.x = (float)((v0 & 15)        - 8) * scale;
    r.y = (float)(((v0 >> 4) & 15) - 8) * scale;
    r.z = (float)((v1 & 15)        - 8) * scale;
    r.w = (float)(((v1 >> 4) & 15) - 8) * scale;

    out[q] = r;
}

extern "C" void kernel_launch(void* const* d_in, const int* in_sizes, int n_in,
                              void* d_out, int out_size)
{
    const int* packed = (const int*)d_in[0];
    float4* out = (float4*)d_out;

    int num_quads = out_size / 4;              // 33,554,432
    int threads = 256;
    int blocks = (num_quads + threads - 1) / threads;

    dequant_mxfp4_kernel<<<blocks, threads>>>(packed, out, num_quads);
}

// round 2
// speedup vs baseline: 1.0867x; 1.0867x over previous
#include <cuda_runtime.h>
#include <cuda_bf16.h>

// Dequant: groups of 17 int32 (16 "byte" ints -> 32 nibbles, 1 scale int).
// out[g*32 + i] = (nibble_i - 8) / 12 * exp2(clamp(scale-127, -126, 127))
//
// One thread produces UNROLL float4s (block-strided so every STG.128 is
// warp-coalesced). 12 independent LDGs per thread keep the DRAM queue full.

#define THREADS 256
#define UNROLL 4
#define QUADS_PER_BLOCK (THREADS * UNROLL)

__global__ void __launch_bounds__(THREADS) dequant_mxfp4_kernel(
    const int* __restrict__ packed,
    float4* __restrict__ out,
    int num_quads)
{
    int q0 = blockIdx.x * QUADS_PER_BLOCK + threadIdx.x;

    int v0[UNROLL], v1[UNROLL], s[UNROLL];

    #pragma unroll
    for (int j = 0; j < UNROLL; j++) {
        int q = q0 + j * THREADS;
        int g   = q >> 3;
        int sub = q & 7;
        int base = g * 17;
        v0[j] = __ldcs(packed + base + sub * 2);
        v1[j] = __ldcs(packed + base + sub * 2 + 1);
        s[j]  = __ldcs(packed + base + 16);
    }

    #pragma unroll
    for (int j = 0; j < UNROLL; j++) {
        int q = q0 + j * THREADS;
        if (q < num_quads) {
            // exp2(clip(s-127,-126,127)) == float with exponent field clamp(s,1,254)
            int e = min(max(s[j], 1), 254);
            float scale = __int_as_float(e << 23) * (1.0f / 12.0f);

            float4 r;
            r.x = (float)((v0[j] & 15)        - 8) * scale;
            r.y = (float)(((v0[j] >> 4) & 15) - 8) * scale;
            r.z = (float)((v1[j] & 15)        - 8) * scale;
            r.w = (float)(((v1[j] >> 4) & 15) - 8) * scale;

            __stcs(out + q, r);
        }
    }
}

extern "C" void kernel_launch(void* const* d_in, const int* in_sizes, int n_in,
                              void* d_out, int out_size)
{
    const int* packed = (const int*)d_in[0];
    float4* out = (float4*)d_out;

    int num_quads = out_size / 4;  // 33,554,432
    int blocks = (num_quads + QUADS_PER_BLOCK - 1) / QUADS_PER_BLOCK;  // 32768

    dequant_mxfp4_kernel<<<blocks, THREADS>>>(packed, out, num_quads);
}

// round 3
// speedup vs baseline: 1.0872x; 1.0005x over previous
#include <cuda_runtime.h>
#include <cuda_bf16.h>

// Dequant: groups of 17 int32 (16 "byte" ints -> 32 nibbles, 1 scale int).
// out[g*32 + i] = (nibble_i - 8) / 12 * exp2(clamp(scale-127, -126, 127))
//
// One thread produces UNROLL float4s (block-strided so every STG.128 is
// warp-coalesced). 24 independent front-batched LDGs per thread keep the
// DRAM queue full.

#define THREADS 256
#define UNROLL 8
#define QUADS_PER_BLOCK (THREADS * UNROLL)

__global__ void __launch_bounds__(THREADS) dequant_mxfp4_kernel(
    const int* __restrict__ packed,
    float4* __restrict__ out,
    int num_quads)
{
    int q0 = blockIdx.x * QUADS_PER_BLOCK + threadIdx.x;

    int v0[UNROLL], v1[UNROLL], s[UNROLL];

    #pragma unroll
    for (int j = 0; j < UNROLL; j++) {
        int q = q0 + j * THREADS;
        int g   = q >> 3;
        int sub = q & 7;
        int base = g * 17;
        v0[j] = __ldcs(packed + base + sub * 2);
        v1[j] = __ldcs(packed + base + sub * 2 + 1);
        s[j]  = __ldcs(packed + base + 16);
    }

    #pragma unroll
    for (int j = 0; j < UNROLL; j++) {
        int q = q0 + j * THREADS;
        if (q < num_quads) {
            // exp2(clip(s-127,-126,127)) == float with exponent field clamp(s,1,254)
            int e = min(max(s[j], 1), 254);
            float scale = __int_as_float(e << 23) * (1.0f / 12.0f);

            float4 r;
            r.x = (float)((v0[j] & 15)        - 8) * scale;
            r.y = (float)(((v0[j] >> 4) & 15) - 8) * scale;
            r.z = (float)((v1[j] & 15)        - 8) * scale;
            r.w = (float)(((v1[j] >> 4) & 15) - 8) * scale;

            __stcs(out + q, r);
        }
    }
}

extern "C" void kernel_launch(void* const* d_in, const int* in_sizes, int n_in,
                              void* d_out, int out_size)
{
    const int* packed = (const int*)d_in[0];
    float4* out = (float4*)d_out;

    int num_quads = out_size / 4;  // 33,554,432
    int blocks = (num_quads + QUADS_PER_BLOCK - 1) / QUADS_PER_BLOCK;  // 16384

    dequant_mxfp4_kernel<<<blocks, THREADS>>>(packed, out, num_quads);
}